// round 15
// baseline (speedup 1.0000x reference)
#include <cuda_runtime.h>
#include <cuda_fp16.h>
#include <cstdint>

// Problem constants (fixed by setup_inputs)
#define BATCH 8
#define HDIM  64
#define WDIM  64
#define CDIM  128
#define FDIM  128
#define KNUM  9
#define NPIX  (BATCH * HDIM * WDIM)      // 32768
#define PIX_PER_CTA 128
#define NCTA  (NPIX / PIX_PER_CTA)       // 256
#define NTHREADS 512

#define ROWB 272                          // bytes per A SMEM row -> conflict-free ldmatrix
#define TILE_BYTES (128 * ROWB)           // 34816
#define SM_A0 0
#define SM_A1 TILE_BYTES
#define SM_BIAS (2 * TILE_BYTES)          // 69632
#define SMEM_BYTES (SM_BIAS + 512)        // 70144 -> 2 CTAs/SM

// TF build(): stack(meshgrid(ij)).reshape(-1,2) pairs:
// (0,0),(0,1),(1,1),(2,2),(2,0),(1,2),(0,1),(2,0),(1,2)
static __device__ const float KOFF_I[KNUM] = {0.f, 0.f, 1.f, 2.f, 2.f, 1.f, 0.f, 2.f, 1.f};
static __device__ const float KOFF_J[KNUM] = {0.f, 1.f, 1.f, 2.f, 0.f, 2.f, 1.f, 0.f, 2.f};

// Weights pre-arranged in mma16816 B-fragment order:
// g_Wf[kn][wn2(2)][ks(8)][q(4)][lane(32)] : uint4 per lane.
#define WFRAG_N (KNUM * 2 * 8 * 4 * 32)
__device__ __align__(16) uint4 g_Wf[WFRAG_N];

// fp16 copy of x: [B][H][W][C] halves, 8.4 MB (L2-resident).
__device__ __align__(16) __half g_xh[NPIX * CDIM];

#define XBLOCKS (NPIX * CDIM / 4 / 256)   // 4096 blocks for x convert
#define WBLOCKS ((WFRAG_N + 255) / 256)   // 72 blocks for weights

// Fused prep: blocks [0, XBLOCKS) convert x to fp16; rest build B fragments.
__global__ void prep_kernel(const float* __restrict__ x, const float* __restrict__ Wsrc) {
    if (blockIdx.x < XBLOCKS) {
        int idx = blockIdx.x * 256 + threadIdx.x;
        float4 v = ((const float4*)x)[idx];
        __half2 h0 = __floats2half2_rn(v.x, v.y);
        __half2 h1 = __floats2half2_rn(v.z, v.w);
        ((uint2*)g_xh)[idx] = make_uint2(*(uint32_t*)&h0, *(uint32_t*)&h1);
        return;
    }
    int idx = (blockIdx.x - XBLOCKS) * 256 + threadIdx.x;
    if (idx >= WFRAG_N) return;
    int l  = idx & 31;
    int q  = (idx >> 5) & 3;
    int ks = (idx >> 7) & 7;
    int wn = (idx >> 10) & 1;
    int kn = idx >> 11;
    int n0 = wn * 64 + q * 16 + (l >> 2);  // output-feature row (N)
    int k0 = ks * 16 + 2 * (l & 3);        // channel col (K)
    #define H2(nn, kk) ({ \
        __half lo_ = __float2half_rn(Wsrc[(kn * 128 + (kk)) * 128 + (nn)]); \
        __half hi_ = __float2half_rn(Wsrc[(kn * 128 + (kk) + 1) * 128 + (nn)]); \
        __half2 p_ = __halves2half2(lo_, hi_); \
        *(uint32_t*)&p_; })
    uint4 v;
    v.x = H2(n0,     k0);
    v.y = H2(n0 + 8, k0);
    v.z = H2(n0,     k0 + 8);
    v.w = H2(n0 + 8, k0 + 8);
    #undef H2
    g_Wf[idx] = v;
}

__device__ __forceinline__ uint32_t smem_u32(const void* p) {
    uint32_t a;
    asm("{ .reg .u64 t; cvta.to.shared.u64 t, %1; cvt.u32.u64 %0, t; }" : "=r"(a) : "l"(p));
    return a;
}

__device__ __forceinline__ void ldsm4(uint32_t r[4], uint32_t addr) {
    asm volatile("ldmatrix.sync.aligned.m8n8.x4.shared.b16 {%0,%1,%2,%3}, [%4];"
                 : "=r"(r[0]), "=r"(r[1]), "=r"(r[2]), "=r"(r[3]) : "r"(addr));
}

__device__ __forceinline__ void mma16816(float d[4], const uint32_t a[4],
                                         uint32_t b0, uint32_t b1) {
    asm volatile(
        "mma.sync.aligned.m16n8k16.row.col.f32.f16.f16.f32 "
        "{%0,%1,%2,%3}, {%4,%5,%6,%7}, {%8,%9}, {%0,%1,%2,%3};"
        : "+f"(d[0]), "+f"(d[1]), "+f"(d[2]), "+f"(d[3])
        : "r"(a[0]), "r"(a[1]), "r"(a[2]), "r"(a[3]), "r"(b0), "r"(b1));
}

// Streaming (evict-first) 8B load: keeps the gather stream from thrashing the
// L1-resident B-fragment working set.
__device__ __forceinline__ uint2 ldcs8(const uint2* p) {
    uint2 v;
    asm volatile("ld.global.cs.nc.v2.u32 {%0,%1}, [%2];"
                 : "=r"(v.x), "=r"(v.y) : "l"(p));
    return v;
}

// Offset prefetch for chunk n: lanes 0-15 hold component (l&1) of pixel
// wid*8 + (l>>1). Issued early; latency drains under the MMA phase.
__device__ __forceinline__ float fetch_offsets(const float* __restrict__ off,
                                               int pix0, int n, int wid, int lid) {
    float v = 0.0f;
    if (lid < 16)
        v = __ldg(&off[(pix0 + wid * 8 + (lid >> 1)) * 18 + 2 * n + (lid & 1)]);
    return v;
}

// Bilinear-sample one chunk's A tile (128 px x 128 ch, 16 warps x 8 px) into
// SMEM. Depth-2 pipelined streaming gathers, all-fp16 blend, offsets via shfl.
__device__ __forceinline__ void sample_chunk(char* smem, int abuf_off, float ov,
                                             int pix0, int n, int wid, int lid) {
    const float ki = KOFF_I[n];
    const float kj = KOFF_J[n];
    const uint2* xb = (const uint2*)g_xh;
    uint2 crn[3][4];
    float fys[3], fxs[3];

    #define LOADPX(i, s) { \
        int P = pix0 + wid * 8 + (i); \
        int bb = P >> 12, hh = (P >> 6) & 63, ww = P & 63; \
        float oy = __shfl_sync(0xffffffffu, ov, 2 * (i)); \
        float ox = __shfl_sync(0xffffffffu, ov, 2 * (i) + 1); \
        float y  = fminf(fmaxf((float)(hh - 1) + ki + oy, 0.0f), 63.0f); \
        float xf = fminf(fmaxf((float)(ww - 1) + kj + ox, 0.0f), 63.0f); \
        int y0 = __float2int_rd(y), x0 = __float2int_rd(xf); \
        float fy = y - (float)y0, fx = xf - (float)x0; \
        int y1 = y0 + (fy > 0.0f);   /* == ceil(y) for clamped y >= 0 */ \
        int x1 = x0 + (fx > 0.0f); \
        fys[s] = fy; fxs[s] = fx; \
        const uint2* base = xb + (size_t)bb * 131072; \
        crn[s][0] = ldcs8(&base[(y0 * 64 + x0) * 32 + lid]); \
        crn[s][1] = ldcs8(&base[(y1 * 64 + x0) * 32 + lid]); \
        crn[s][2] = ldcs8(&base[(y0 * 64 + x1) * 32 + lid]); \
        crn[s][3] = ldcs8(&base[(y1 * 64 + x1) * 32 + lid]); \
    }

    LOADPX(0, 0)
    LOADPX(1, 1)
    #pragma unroll
    for (int i = 0; i < 8; i++) {
        const int s = i % 3;
        if (i + 2 < 8) { LOADPX(i + 2, (i + 2) % 3) }
        float fy = fys[s], fx = fxs[s];
        float gy = 1.0f - fy, gx = 1.0f - fx;
        __half2 wlt = __float2half2_rn(gy * gx);
        __half2 wrt = __float2half2_rn(fy * gx);
        __half2 wlb = __float2half2_rn(gy * fx);
        __half2 wrb = __float2half2_rn(fy * fx);

        __half2 v0 = __hmul2(*(__half2*)&crn[s][0].x, wlt);
        v0 = __hfma2(*(__half2*)&crn[s][1].x, wrt, v0);
        v0 = __hfma2(*(__half2*)&crn[s][2].x, wlb, v0);
        v0 = __hfma2(*(__half2*)&crn[s][3].x, wrb, v0);
        __half2 v1 = __hmul2(*(__half2*)&crn[s][0].y, wlt);
        v1 = __hfma2(*(__half2*)&crn[s][1].y, wrt, v1);
        v1 = __hfma2(*(__half2*)&crn[s][2].y, wlb, v1);
        v1 = __hfma2(*(__half2*)&crn[s][3].y, wrb, v1);

        uint2 st = make_uint2(*(uint32_t*)&v0, *(uint32_t*)&v1);
        *(uint2*)(smem + abuf_off + (wid * 8 + i) * ROWB + lid * 8) = st;
    }
    #undef LOADPX
}

__global__ __launch_bounds__(NTHREADS, 2)
void deform_conv_kernel(const float* __restrict__ off,
                        const float* __restrict__ bias,
                        float* __restrict__ out) {
    extern __shared__ char smem[];
    uint32_t sb = smem_u32(smem);
    float* bsm = (float*)(smem + SM_BIAS);

    const int tid = threadIdx.x;
    const int wid = tid >> 5;
    const int lid = tid & 31;
    const int g   = lid >> 2;
    const int tig = lid & 3;
    const int wm  = wid & 3;    // warp row block (32 pixels)
    const int wn  = wid >> 2;   // warp col block (32 F)
    const int pix0 = blockIdx.x * PIX_PER_CTA;

    if (tid < 128) bsm[tid] = bias[tid];

    float acc[2][4][4];
    #pragma unroll
    for (int mt = 0; mt < 2; mt++)
        #pragma unroll
        for (int nt = 0; nt < 4; nt++)
            #pragma unroll
            for (int q = 0; q < 4; q++) acc[mt][nt][q] = 0.0f;

    // ---- Prologue: sample chunk 0 into A0, prefetch chunk-1 offsets ----
    {
        float ov0 = fetch_offsets(off, pix0, 0, wid, lid);
        sample_chunk(smem, SM_A0, ov0, pix0, 0, wid, lid);
    }
    float ov = fetch_offsets(off, pix0, 1, wid, lid);
    __syncthreads();

    int cur = 0;
    for (int n = 0; n < KNUM; n++) {
        // prefetch chunk n+2 offsets; latency hides under the MMA phase
        float ovn = (n + 2 < KNUM) ? fetch_offsets(off, pix0, n + 2, wid, lid) : 0.0f;

        const uint32_t Abase = sb + (cur ? SM_A1 : SM_A0)
                             + (wm * 32 + (lid & 15)) * ROWB + (lid >> 4) * 16;
        const uint4* wb = g_Wf + ((n * 2 + (wn >> 1)) * 8) * 4 * 32 + lid;
        const int qb = (wn & 1) * 2;

        // ---- MMA: warp tile 32(M) x 32(N); B strips L1-resident (default policy) ----
        #pragma unroll
        for (int ks = 0; ks < 8; ks++) {
            uint4 b0 = __ldg(wb + (ks * 4 + qb) * 32);
            uint4 b1 = __ldg(wb + (ks * 4 + qb + 1) * 32);
            uint32_t a[4];
            ldsm4(a, Abase + ks * 32);
            mma16816(acc[0][0], a, b0.x, b0.z);
            mma16816(acc[0][1], a, b0.y, b0.w);
            mma16816(acc[0][2], a, b1.x, b1.z);
            mma16816(acc[0][3], a, b1.y, b1.w);
            ldsm4(a, Abase + 16 * ROWB + ks * 32);
            mma16816(acc[1][0], a, b0.x, b0.z);
            mma16816(acc[1][1], a, b0.y, b0.w);
            mma16816(acc[1][2], a, b1.x, b1.z);
            mma16816(acc[1][3], a, b1.y, b1.w);
        }

        // ---- Sample chunk n+1 into the other A buffer ----
        if (n + 1 < KNUM)
            sample_chunk(smem, cur ? SM_A0 : SM_A1, ov, pix0, n + 1, wid, lid);

        __syncthreads();
        ov = ovn;
        cur ^= 1;
    }

    // ---- Epilogue: add bias, store fp32 output ----
    #pragma unroll
    for (int mt = 0; mt < 2; mt++) {
        #pragma unroll
        for (int nt = 0; nt < 4; nt++) {
            int col = wn * 32 + nt * 8 + tig * 2;
            float b0 = bsm[col], b1 = bsm[col + 1];
            int row = pix0 + wm * 32 + mt * 16 + g;
            *(float2*)(out + (size_t)row * FDIM + col) =
                make_float2(acc[mt][nt][0] + b0, acc[mt][nt][1] + b1);
            *(float2*)(out + (size_t)(row + 8) * FDIM + col) =
                make_float2(acc[mt][nt][2] + b0, acc[mt][nt][3] + b1);
        }
    }
}

extern "C" void kernel_launch(void* const* d_in, const int* in_sizes, int n_in,
                              void* d_out, int out_size) {
    const float* x   = (const float*)d_in[0];
    const float* off = (const float*)d_in[1];
    const float* Wk  = (const float*)d_in[2];
    const float* b   = (const float*)d_in[3];
    float* out = (float*)d_out;

    cudaFuncSetAttribute(deform_conv_kernel,
                         cudaFuncAttributeMaxDynamicSharedMemorySize, SMEM_BYTES);

    prep_kernel<<<XBLOCKS + WBLOCKS, 256>>>(x, Wk);
    deform_conv_kernel<<<NCTA, NTHREADS, SMEM_BYTES>>>(off, b, out);
}

// round 16
// speedup vs baseline: 1.5440x; 1.5440x over previous
#include <cuda_runtime.h>
#include <cuda_fp16.h>
#include <cstdint>

// Problem constants (fixed by setup_inputs)
#define BATCH 8
#define HDIM  64
#define WDIM  64
#define CDIM  128
#define FDIM  128
#define KNUM  9
#define NPIX  (BATCH * HDIM * WDIM)      // 32768
#define PIX_PER_CTA 64
#define NCTA  (NPIX / PIX_PER_CTA)       // 512
#define NTHREADS 256

#define ROWB 272                          // bytes per A SMEM row -> conflict-free ldmatrix
#define TILE_BYTES (64 * ROWB)            // 17408
#define SM_A0 0
#define SM_A1 TILE_BYTES
#define SM_BIAS (2 * TILE_BYTES)          // 34816
#define SMEM_BYTES (SM_BIAS + 512)        // 35328 -> 4 CTAs/SM (141 KB)

// TF build(): stack(meshgrid(ij)).reshape(-1,2) pairs:
// (0,0),(0,1),(1,1),(2,2),(2,0),(1,2),(0,1),(2,0),(1,2)
static __device__ const float KOFF_I[KNUM] = {0.f, 0.f, 1.f, 2.f, 2.f, 1.f, 0.f, 2.f, 1.f};
static __device__ const float KOFF_J[KNUM] = {0.f, 1.f, 1.f, 2.f, 0.f, 2.f, 1.f, 0.f, 2.f};

// Weights pre-arranged in mma16816 B-fragment order:
// g_Wf[kn][wn2(2)][ks(8)][q(4)][lane(32)] : uint4 per lane.
#define WFRAG_N (KNUM * 2 * 8 * 4 * 32)
__device__ __align__(16) uint4 g_Wf[WFRAG_N];

// fp16 copy of x: [B][H][W][C] halves, 8.4 MB (L2-resident).
__device__ __align__(16) __half g_xh[NPIX * CDIM];

#define XQUADS (NPIX * CDIM / 4)          // 1048576 float4s
#define XBLOCKS (XQUADS / 512)            // 2048 blocks, 2 float4 per thread
#define WBLOCKS ((WFRAG_N + 255) / 256)   // 72 blocks for weights

// Fused prep: blocks [0, XBLOCKS) convert x to fp16 (2 quads/thread, MLP=2);
// remaining blocks build B fragments.
__global__ void prep_kernel(const float* __restrict__ x, const float* __restrict__ Wsrc) {
    if (blockIdx.x < XBLOCKS) {
        int i0 = blockIdx.x * 256 + threadIdx.x;
        int i1 = i0 + XBLOCKS * 256;
        float4 v0 = ((const float4*)x)[i0];
        float4 v1 = ((const float4*)x)[i1];
        __half2 a0 = __floats2half2_rn(v0.x, v0.y);
        __half2 a1 = __floats2half2_rn(v0.z, v0.w);
        __half2 b0 = __floats2half2_rn(v1.x, v1.y);
        __half2 b1 = __floats2half2_rn(v1.z, v1.w);
        ((uint2*)g_xh)[i0] = make_uint2(*(uint32_t*)&a0, *(uint32_t*)&a1);
        ((uint2*)g_xh)[i1] = make_uint2(*(uint32_t*)&b0, *(uint32_t*)&b1);
        return;
    }
    int idx = (blockIdx.x - XBLOCKS) * 256 + threadIdx.x;
    if (idx >= WFRAG_N) return;
    int l  = idx & 31;
    int q  = (idx >> 5) & 3;
    int ks = (idx >> 7) & 7;
    int wn = (idx >> 10) & 1;
    int kn = idx >> 11;
    int n0 = wn * 64 + q * 16 + (l >> 2);  // output-feature row (N)
    int k0 = ks * 16 + 2 * (l & 3);        // channel col (K)
    #define H2(nn, kk) ({ \
        __half lo_ = __float2half_rn(Wsrc[(kn * 128 + (kk)) * 128 + (nn)]); \
        __half hi_ = __float2half_rn(Wsrc[(kn * 128 + (kk) + 1) * 128 + (nn)]); \
        __half2 p_ = __halves2half2(lo_, hi_); \
        *(uint32_t*)&p_; })
    uint4 v;
    v.x = H2(n0,     k0);
    v.y = H2(n0 + 8, k0);
    v.z = H2(n0,     k0 + 8);
    v.w = H2(n0 + 8, k0 + 8);
    #undef H2
    g_Wf[idx] = v;
}

__device__ __forceinline__ uint32_t smem_u32(const void* p) {
    uint32_t a;
    asm("{ .reg .u64 t; cvta.to.shared.u64 t, %1; cvt.u32.u64 %0, t; }" : "=r"(a) : "l"(p));
    return a;
}

__device__ __forceinline__ void ldsm4(uint32_t r[4], uint32_t addr) {
    asm volatile("ldmatrix.sync.aligned.m8n8.x4.shared.b16 {%0,%1,%2,%3}, [%4];"
                 : "=r"(r[0]), "=r"(r[1]), "=r"(r[2]), "=r"(r[3]) : "r"(addr));
}

__device__ __forceinline__ void mma16816(float d[4], const uint32_t a[4],
                                         uint32_t b0, uint32_t b1) {
    asm volatile(
        "mma.sync.aligned.m16n8k16.row.col.f32.f16.f16.f32 "
        "{%0,%1,%2,%3}, {%4,%5,%6,%7}, {%8,%9}, {%0,%1,%2,%3};"
        : "+f"(d[0]), "+f"(d[1]), "+f"(d[2]), "+f"(d[3])
        : "r"(a[0]), "r"(a[1]), "r"(a[2]), "r"(a[3]), "r"(b0), "r"(b1));
}

// Offset prefetch for chunk n: lanes 0-15 hold component (l&1) of pixel
// wid*8 + (l>>1). Issued early; latency drains under the MMA phase.
__device__ __forceinline__ float fetch_offsets(const float* __restrict__ off,
                                               int pix0, int n, int wid, int lid) {
    float v = 0.0f;
    if (lid < 16)
        v = __ldg(&off[(pix0 + wid * 8 + (lid >> 1)) * 18 + 2 * n + (lid & 1)]);
    return v;
}

// Bilinear-sample one chunk's A tile (64 px x 128 ch, 8 warps x 8 px) into
// SMEM. Depth-2 pipelined gathers (default cache policy -- L1 reuse between
// neighboring pixels is real, R14 proved evict-first loses), all-fp16 blend.
__device__ __forceinline__ void sample_chunk(char* smem, int abuf_off, float ov,
                                             int pix0, int n, int wid, int lid) {
    const float ki = KOFF_I[n];
    const float kj = KOFF_J[n];
    const uint2* xb = (const uint2*)g_xh;
    uint2 crn[3][4];
    float fys[3], fxs[3];

    #define LOADPX(i, s) { \
        int P = pix0 + wid * 8 + (i); \
        int bb = P >> 12, hh = (P >> 6) & 63, ww = P & 63; \
        float oy = __shfl_sync(0xffffffffu, ov, 2 * (i)); \
        float ox = __shfl_sync(0xffffffffu, ov, 2 * (i) + 1); \
        float y  = fminf(fmaxf((float)(hh - 1) + ki + oy, 0.0f), 63.0f); \
        float xf = fminf(fmaxf((float)(ww - 1) + kj + ox, 0.0f), 63.0f); \
        float y0f = floorf(y), x0f = floorf(xf); \
        int y0 = (int)y0f, y1 = (int)ceilf(y); \
        int x0 = (int)x0f, x1 = (int)ceilf(xf); \
        fys[s] = y - y0f; fxs[s] = xf - x0f; \
        const uint2* base = xb + (size_t)bb * 131072; \
        crn[s][0] = __ldg(&base[(y0 * 64 + x0) * 32 + lid]); \
        crn[s][1] = __ldg(&base[(y1 * 64 + x0) * 32 + lid]); \
        crn[s][2] = __ldg(&base[(y0 * 64 + x1) * 32 + lid]); \
        crn[s][3] = __ldg(&base[(y1 * 64 + x1) * 32 + lid]); \
    }

    LOADPX(0, 0)
    LOADPX(1, 1)
    #pragma unroll
    for (int i = 0; i < 8; i++) {
        const int s = i % 3;
        if (i + 2 < 8) { LOADPX(i + 2, (i + 2) % 3) }
        float fy = fys[s], fx = fxs[s];
        float gy = 1.0f - fy, gx = 1.0f - fx;
        __half2 wlt = __float2half2_rn(gy * gx);
        __half2 wrt = __float2half2_rn(fy * gx);
        __half2 wlb = __float2half2_rn(gy * fx);
        __half2 wrb = __float2half2_rn(fy * fx);

        __half2 v0 = __hmul2(*(__half2*)&crn[s][0].x, wlt);
        v0 = __hfma2(*(__half2*)&crn[s][1].x, wrt, v0);
        v0 = __hfma2(*(__half2*)&crn[s][2].x, wlb, v0);
        v0 = __hfma2(*(__half2*)&crn[s][3].x, wrb, v0);
        __half2 v1 = __hmul2(*(__half2*)&crn[s][0].y, wlt);
        v1 = __hfma2(*(__half2*)&crn[s][1].y, wrt, v1);
        v1 = __hfma2(*(__half2*)&crn[s][2].y, wlb, v1);
        v1 = __hfma2(*(__half2*)&crn[s][3].y, wrb, v1);

        uint2 st = make_uint2(*(uint32_t*)&v0, *(uint32_t*)&v1);
        *(uint2*)(smem + abuf_off + (wid * 8 + i) * ROWB + lid * 8) = st;
    }
    #undef LOADPX
}

__global__ __launch_bounds__(NTHREADS, 4)
void deform_conv_kernel(const float* __restrict__ off,
                        const float* __restrict__ bias,
                        float* __restrict__ out) {
    extern __shared__ char smem[];
    uint32_t sb = smem_u32(smem);
    float* bsm = (float*)(smem + SM_BIAS);

    const int tid = threadIdx.x;
    const int wid = tid >> 5;
    const int lid = tid & 31;
    const int g   = lid >> 2;
    const int tig = lid & 3;
    const int wm  = wid & 1;    // warp row block (32 pixels)
    const int wn  = wid >> 1;   // warp col block (32 F)
    const int pix0 = blockIdx.x * PIX_PER_CTA;

    if (tid < 128) bsm[tid] = bias[tid];

    float acc[2][4][4];
    #pragma unroll
    for (int mt = 0; mt < 2; mt++)
        #pragma unroll
        for (int nt = 0; nt < 4; nt++)
            #pragma unroll
            for (int q = 0; q < 4; q++) acc[mt][nt][q] = 0.0f;

    // ---- Prologue: sample chunk 0 into A0, prefetch chunk-1 offsets ----
    {
        float ov0 = fetch_offsets(off, pix0, 0, wid, lid);
        sample_chunk(smem, SM_A0, ov0, pix0, 0, wid, lid);
    }
    float ov = fetch_offsets(off, pix0, 1, wid, lid);
    __syncthreads();

    int cur = 0;
    for (int n = 0; n < KNUM; n++) {
        // prefetch chunk n+2 offsets; latency hides under the MMA phase
        float ovn = (n + 2 < KNUM) ? fetch_offsets(off, pix0, n + 2, wid, lid) : 0.0f;

        const uint32_t Abase = sb + (cur ? SM_A1 : SM_A0)
                             + (wm * 32 + (lid & 15)) * ROWB + (lid >> 4) * 16;
        const uint4* wb = g_Wf + ((n * 2 + (wn >> 1)) * 8) * 4 * 32 + lid;
        const int qb = (wn & 1) * 2;

        // ---- MMA: warp tile 32(M) x 32(N); B strips shared by 2 m-warps + L1 ----
        #pragma unroll
        for (int ks = 0; ks < 8; ks++) {
            uint4 b0 = __ldg(wb + (ks * 4 + qb) * 32);
            uint4 b1 = __ldg(wb + (ks * 4 + qb + 1) * 32);
            uint32_t a[4];
            ldsm4(a, Abase + ks * 32);
            mma16816(acc[0][0], a, b0.x, b0.z);
            mma16816(acc[0][1], a, b0.y, b0.w);
            mma16816(acc[0][2], a, b1.x, b1.z);
            mma16816(acc[0][3], a, b1.y, b1.w);
            ldsm4(a, Abase + 16 * ROWB + ks * 32);
            mma16816(acc[1][0], a, b0.x, b0.z);
            mma16816(acc[1][1], a, b0.y, b0.w);
            mma16816(acc[1][2], a, b1.x, b1.z);
            mma16816(acc[1][3], a, b1.y, b1.w);
        }

        // ---- Sample chunk n+1 into the other A buffer ----
        if (n + 1 < KNUM)
            sample_chunk(smem, cur ? SM_A0 : SM_A1, ov, pix0, n + 1, wid, lid);

        __syncthreads();
        ov = ovn;
        cur ^= 1;
    }

    // ---- Epilogue: add bias, store fp32 output ----
    #pragma unroll
    for (int mt = 0; mt < 2; mt++) {
        #pragma unroll
        for (int nt = 0; nt < 4; nt++) {
            int col = wn * 32 + nt * 8 + tig * 2;
            float b0 = bsm[col], b1 = bsm[col + 1];
            int row = pix0 + wm * 32 + mt * 16 + g;
            *(float2*)(out + (size_t)row * FDIM + col) =
                make_float2(acc[mt][nt][0] + b0, acc[mt][nt][1] + b1);
            *(float2*)(out + (size_t)(row + 8) * FDIM + col) =
                make_float2(acc[mt][nt][2] + b0, acc[mt][nt][3] + b1);
        }
    }
}

extern "C" void kernel_launch(void* const* d_in, const int* in_sizes, int n_in,
                              void* d_out, int out_size) {
    const float* x   = (const float*)d_in[0];
    const float* off = (const float*)d_in[1];
    const float* Wk  = (const float*)d_in[2];
    const float* b   = (const float*)d_in[3];
    float* out = (float*)d_out;

    cudaFuncSetAttribute(deform_conv_kernel,
                         cudaFuncAttributeMaxDynamicSharedMemorySize, SMEM_BYTES);

    prep_kernel<<<XBLOCKS + WBLOCKS, 256>>>(x, Wk);
    deform_conv_kernel<<<NCTA, NTHREADS, SMEM_BYTES>>>(off, b, out);
}

// round 17
// speedup vs baseline: 1.6773x; 1.0864x over previous
#include <cuda_runtime.h>
#include <cuda_fp16.h>
#include <cstdint>

// Problem constants (fixed by setup_inputs)
#define BATCH 8
#define HDIM  64
#define WDIM  64
#define CDIM  128
#define FDIM  128
#define KNUM  9
#define NPIX  (BATCH * HDIM * WDIM)      // 32768
#define PIX_PER_CTA 32
#define NCTA  (NPIX / PIX_PER_CTA)       // 1024
#define NTHREADS 128

#define ROWB 272                          // bytes per A SMEM row -> conflict-free ldmatrix
#define TILE_BYTES (32 * ROWB)            // 8704
#define SM_A0 0
#define SM_A1 TILE_BYTES
#define SM_BIAS (2 * TILE_BYTES)          // 17408
#define SMEM_BYTES (SM_BIAS + 512)        // 17920 -> 8 CTAs/SM (143 KB)

// TF build(): stack(meshgrid(ij)).reshape(-1,2) pairs:
// (0,0),(0,1),(1,1),(2,2),(2,0),(1,2),(0,1),(2,0),(1,2)
static __device__ const float KOFF_I[KNUM] = {0.f, 0.f, 1.f, 2.f, 2.f, 1.f, 0.f, 2.f, 1.f};
static __device__ const float KOFF_J[KNUM] = {0.f, 1.f, 1.f, 2.f, 0.f, 2.f, 1.f, 0.f, 2.f};

// Weights pre-arranged in mma16816 B-fragment order:
// g_Wf[kn][wn2(2)][ks(8)][q(4)][lane(32)] : uint4 per lane.
#define WFRAG_N (KNUM * 2 * 8 * 4 * 32)
__device__ __align__(16) uint4 g_Wf[WFRAG_N];

// fp16 copy of x: [B][H][W][C] halves, 8.4 MB (L2-resident).
__device__ __align__(16) __half g_xh[NPIX * CDIM];

#define XQUADS (NPIX * CDIM / 4)          // 1048576 float4s
#define XBLOCKS (XQUADS / 512)            // 2048 blocks, 2 float4 per thread
#define WBLOCKS ((WFRAG_N + 255) / 256)   // 72 blocks for weights

// Fused prep: blocks [0, XBLOCKS) convert x to fp16 (2 quads/thread, MLP=2);
// remaining blocks build B fragments.
__global__ void prep_kernel(const float* __restrict__ x, const float* __restrict__ Wsrc) {
    if (blockIdx.x < XBLOCKS) {
        int i0 = blockIdx.x * 256 + threadIdx.x;
        int i1 = i0 + XBLOCKS * 256;
        float4 v0 = ((const float4*)x)[i0];
        float4 v1 = ((const float4*)x)[i1];
        __half2 a0 = __floats2half2_rn(v0.x, v0.y);
        __half2 a1 = __floats2half2_rn(v0.z, v0.w);
        __half2 b0 = __floats2half2_rn(v1.x, v1.y);
        __half2 b1 = __floats2half2_rn(v1.z, v1.w);
        ((uint2*)g_xh)[i0] = make_uint2(*(uint32_t*)&a0, *(uint32_t*)&a1);
        ((uint2*)g_xh)[i1] = make_uint2(*(uint32_t*)&b0, *(uint32_t*)&b1);
        return;
    }
    int idx = (blockIdx.x - XBLOCKS) * 256 + threadIdx.x;
    if (idx >= WFRAG_N) return;
    int l  = idx & 31;
    int q  = (idx >> 5) & 3;
    int ks = (idx >> 7) & 7;
    int wn = (idx >> 10) & 1;
    int kn = idx >> 11;
    int n0 = wn * 64 + q * 16 + (l >> 2);  // output-feature row (N)
    int k0 = ks * 16 + 2 * (l & 3);        // channel col (K)
    #define H2(nn, kk) ({ \
        __half lo_ = __float2half_rn(Wsrc[(kn * 128 + (kk)) * 128 + (nn)]); \
        __half hi_ = __float2half_rn(Wsrc[(kn * 128 + (kk) + 1) * 128 + (nn)]); \
        __half2 p_ = __halves2half2(lo_, hi_); \
        *(uint32_t*)&p_; })
    uint4 v;
    v.x = H2(n0,     k0);
    v.y = H2(n0 + 8, k0);
    v.z = H2(n0,     k0 + 8);
    v.w = H2(n0 + 8, k0 + 8);
    #undef H2
    g_Wf[idx] = v;
}

__device__ __forceinline__ uint32_t smem_u32(const void* p) {
    uint32_t a;
    asm("{ .reg .u64 t; cvta.to.shared.u64 t, %1; cvt.u32.u64 %0, t; }" : "=r"(a) : "l"(p));
    return a;
}

__device__ __forceinline__ void ldsm4(uint32_t r[4], uint32_t addr) {
    asm volatile("ldmatrix.sync.aligned.m8n8.x4.shared.b16 {%0,%1,%2,%3}, [%4];"
                 : "=r"(r[0]), "=r"(r[1]), "=r"(r[2]), "=r"(r[3]) : "r"(addr));
}

__device__ __forceinline__ void mma16816(float d[4], const uint32_t a[4],
                                         uint32_t b0, uint32_t b1) {
    asm volatile(
        "mma.sync.aligned.m16n8k16.row.col.f32.f16.f16.f32 "
        "{%0,%1,%2,%3}, {%4,%5,%6,%7}, {%8,%9}, {%0,%1,%2,%3};"
        : "+f"(d[0]), "+f"(d[1]), "+f"(d[2]), "+f"(d[3])
        : "r"(a[0]), "r"(a[1]), "r"(a[2]), "r"(a[3]), "r"(b0), "r"(b1));
}

// Offset prefetch for chunk n: lanes 0-15 hold component (l&1) of pixel
// wid*8 + (l>>1). Issued early; latency drains under the MMA phase.
__device__ __forceinline__ float fetch_offsets(const float* __restrict__ off,
                                               int pix0, int n, int wid, int lid) {
    float v = 0.0f;
    if (lid < 16)
        v = __ldg(&off[(pix0 + wid * 8 + (lid >> 1)) * 18 + 2 * n + (lid & 1)]);
    return v;
}

// Bilinear-sample one chunk's A tile (32 px x 128 ch, 4 warps x 8 px) into
// SMEM. Depth-2 pipelined gathers (default cache policy -- L1 reuse between
// neighboring pixels is real, R14 proved evict-first loses), all-fp16 blend.
__device__ __forceinline__ void sample_chunk(char* smem, int abuf_off, float ov,
                                             int pix0, int n, int wid, int lid) {
    const float ki = KOFF_I[n];
    const float kj = KOFF_J[n];
    const uint2* xb = (const uint2*)g_xh;
    uint2 crn[3][4];
    float fys[3], fxs[3];

    #define LOADPX(i, s) { \
        int P = pix0 + wid * 8 + (i); \
        int bb = P >> 12, hh = (P >> 6) & 63, ww = P & 63; \
        float oy = __shfl_sync(0xffffffffu, ov, 2 * (i)); \
        float ox = __shfl_sync(0xffffffffu, ov, 2 * (i) + 1); \
        float y  = fminf(fmaxf((float)(hh - 1) + ki + oy, 0.0f), 63.0f); \
        float xf = fminf(fmaxf((float)(ww - 1) + kj + ox, 0.0f), 63.0f); \
        float y0f = floorf(y), x0f = floorf(xf); \
        int y0 = (int)y0f, y1 = (int)ceilf(y); \
        int x0 = (int)x0f, x1 = (int)ceilf(xf); \
        fys[s] = y - y0f; fxs[s] = xf - x0f; \
        const uint2* base = xb + (size_t)bb * 131072; \
        crn[s][0] = __ldg(&base[(y0 * 64 + x0) * 32 + lid]); \
        crn[s][1] = __ldg(&base[(y1 * 64 + x0) * 32 + lid]); \
        crn[s][2] = __ldg(&base[(y0 * 64 + x1) * 32 + lid]); \
        crn[s][3] = __ldg(&base[(y1 * 64 + x1) * 32 + lid]); \
    }

    LOADPX(0, 0)
    LOADPX(1, 1)
    #pragma unroll
    for (int i = 0; i < 8; i++) {
        const int s = i % 3;
        if (i + 2 < 8) { LOADPX(i + 2, (i + 2) % 3) }
        float fy = fys[s], fx = fxs[s];
        float gy = 1.0f - fy, gx = 1.0f - fx;
        __half2 wlt = __float2half2_rn(gy * gx);
        __half2 wrt = __float2half2_rn(fy * gx);
        __half2 wlb = __float2half2_rn(gy * fx);
        __half2 wrb = __float2half2_rn(fy * fx);

        __half2 v0 = __hmul2(*(__half2*)&crn[s][0].x, wlt);
        v0 = __hfma2(*(__half2*)&crn[s][1].x, wrt, v0);
        v0 = __hfma2(*(__half2*)&crn[s][2].x, wlb, v0);
        v0 = __hfma2(*(__half2*)&crn[s][3].x, wrb, v0);
        __half2 v1 = __hmul2(*(__half2*)&crn[s][0].y, wlt);
        v1 = __hfma2(*(__half2*)&crn[s][1].y, wrt, v1);
        v1 = __hfma2(*(__half2*)&crn[s][2].y, wlb, v1);
        v1 = __hfma2(*(__half2*)&crn[s][3].y, wrb, v1);

        uint2 st = make_uint2(*(uint32_t*)&v0, *(uint32_t*)&v1);
        *(uint2*)(smem + abuf_off + (wid * 8 + i) * ROWB + lid * 8) = st;
    }
    #undef LOADPX
}

__global__ __launch_bounds__(NTHREADS, 8)
void deform_conv_kernel(const float* __restrict__ off,
                        const float* __restrict__ bias,
                        float* __restrict__ out) {
    extern __shared__ char smem[];
    uint32_t sb = smem_u32(smem);
    float* bsm = (float*)(smem + SM_BIAS);

    const int tid = threadIdx.x;
    const int wid = tid >> 5;   // warp = N block (32 cols); all warps span all 32 px
    const int lid = tid & 31;
    const int g   = lid >> 2;
    const int tig = lid & 3;
    const int pix0 = blockIdx.x * PIX_PER_CTA;

    bsm[tid] = bias[tid];

    float acc[2][4][4];
    #pragma unroll
    for (int mt = 0; mt < 2; mt++)
        #pragma unroll
        for (int nt = 0; nt < 4; nt++)
            #pragma unroll
            for (int q = 0; q < 4; q++) acc[mt][nt][q] = 0.0f;

    // ---- Prologue: sample chunk 0 into A0, prefetch chunk-1 offsets ----
    {
        float ov0 = fetch_offsets(off, pix0, 0, wid, lid);
        sample_chunk(smem, SM_A0, ov0, pix0, 0, wid, lid);
    }
    float ov = fetch_offsets(off, pix0, 1, wid, lid);
    __syncthreads();

    int cur = 0;
    for (int n = 0; n < KNUM; n++) {
        // prefetch chunk n+2 offsets; latency hides under the MMA phase
        float ovn = (n + 2 < KNUM) ? fetch_offsets(off, pix0, n + 2, wid, lid) : 0.0f;

        const uint32_t Abase = sb + (cur ? SM_A1 : SM_A0)
                             + (lid & 15) * ROWB + (lid >> 4) * 16;
        const uint4* wb = g_Wf + ((n * 2 + (wid >> 1)) * 8) * 4 * 32 + lid;
        const int qb = (wid & 1) * 2;

        // ---- MMA: warp tile 32(M) x 32(N); each warp owns a distinct B strip ----
        #pragma unroll
        for (int ks = 0; ks < 8; ks++) {
            uint4 b0 = __ldg(wb + (ks * 4 + qb) * 32);
            uint4 b1 = __ldg(wb + (ks * 4 + qb + 1) * 32);
            uint32_t a[4];
            ldsm4(a, Abase + ks * 32);
            mma16816(acc[0][0], a, b0.x, b0.z);
            mma16816(acc[0][1], a, b0.y, b0.w);
            mma16816(acc[0][2], a, b1.x, b1.z);
            mma16816(acc[0][3], a, b1.y, b1.w);
            ldsm4(a, Abase + 16 * ROWB + ks * 32);
            mma16816(acc[1][0], a, b0.x, b0.z);
            mma16816(acc[1][1], a, b0.y, b0.w);
            mma16816(acc[1][2], a, b1.x, b1.z);
            mma16816(acc[1][3], a, b1.y, b1.w);
        }

        // ---- Sample chunk n+1 into the other A buffer ----
        if (n + 1 < KNUM)
            sample_chunk(smem, cur ? SM_A0 : SM_A1, ov, pix0, n + 1, wid, lid);

        __syncthreads();
        ov = ovn;
        cur ^= 1;
    }

    // ---- Epilogue: add bias, store fp32 output ----
    #pragma unroll
    for (int mt = 0; mt < 2; mt++) {
        #pragma unroll
        for (int nt = 0; nt < 4; nt++) {
            int col = wid * 32 + nt * 8 + tig * 2;
            float b0 = bsm[col], b1 = bsm[col + 1];
            int row = pix0 + mt * 16 + g;
            *(float2*)(out + (size_t)row * FDIM + col) =
                make_float2(acc[mt][nt][0] + b0, acc[mt][nt][1] + b1);
            *(float2*)(out + (size_t)(row + 8) * FDIM + col) =
                make_float2(acc[mt][nt][2] + b0, acc[mt][nt][3] + b1);
        }
    }
}

extern "C" void kernel_launch(void* const* d_in, const int* in_sizes, int n_in,
                              void* d_out, int out_size) {
    const float* x   = (const float*)d_in[0];
    const float* off = (const float*)d_in[1];
    const float* Wk  = (const float*)d_in[2];
    const float* b   = (const float*)d_in[3];
    float* out = (float*)d_out;

    cudaFuncSetAttribute(deform_conv_kernel,
                         cudaFuncAttributeMaxDynamicSharedMemorySize, SMEM_BYTES);

    prep_kernel<<<XBLOCKS + WBLOCKS, 256>>>(x, Wk);
    deform_conv_kernel<<<NCTA, NTHREADS, SMEM_BYTES>>>(off, b, out);
}